// round 2
// baseline (speedup 1.0000x reference)
#include <cuda_runtime.h>
#include <cuda_bf16.h>
#include <math.h>

// Problem constants
#define SS 1024   // sequence length S
#define BB 32     // batch B
#define DD 1024   // model dim D

// Scratch (device globals — allocation-guard-safe)
__device__ float g_prob[(size_t)BB * SS * SS];   // (B, S, S) row-normalized, row-gated
__device__ float g_pred[SS * BB];                // (S, B)
__device__ float g_valid[BB * SS];               // (B, S) 1.0 = valid (not pad)
__device__ float g_slen[BB];
__device__ float g_lang[BB];
__device__ int   g_mask_is_i32;                  // 1 if mask delivered as int32

// ---------------------------------------------------------------------------
// K-1: sniff the mask dtype. Safe under both layouts: reads 8192 int32 words
// = 32768 bytes, which is exactly the uint8 buffer size and 1/4 of the int32
// buffer. If uint8-packed bools, some word has a nonzero byte above the LSB
// (values > 1) with overwhelming probability for a random ~50% mask.
// Single block so we can decide with one __syncthreads.
// ---------------------------------------------------------------------------
__global__ void sniff_kernel(const int* __restrict__ m) {
    __shared__ int bad[256];
    int tid = threadIdx.x;
    int any = 0;
#pragma unroll
    for (int t = 0; t < 32; t++) {
        int v = m[t * 256 + tid];
        any |= ((unsigned)v > 1u) ? 1 : 0;
    }
    bad[tid] = any;
    __syncthreads();
    if (tid == 0) {
        int a = 0;
        for (int k = 0; k < 256; k++) a |= bad[k];
        g_mask_is_i32 = a ? 0 : 1;   // any word >1 -> packed uint8
    }
}

// ---------------------------------------------------------------------------
// K0: expand mask to float valid array + per-batch reduction.
// One block per batch, 1024 threads (one per position).
// ---------------------------------------------------------------------------
__global__ __launch_bounds__(1024) void mask_kernel(const void* __restrict__ maskp) {
    int b = blockIdx.x;
    int j = threadIdx.x;

    int is_i32 = g_mask_is_i32;
    int mv;
    if (is_i32) mv = ((const int*)maskp)[b * SS + j];
    else        mv = ((const unsigned char*)maskp)[b * SS + j];

    float valid = (mv == 0) ? 1.0f : 0.0f;
    g_valid[b * SS + j] = valid;

    // reduce count of valid
    __shared__ float red[32];
    float c = valid;
#pragma unroll
    for (int o = 16; o; o >>= 1) c += __shfl_xor_sync(0xFFFFFFFFu, c, o);
    if ((j & 31) == 0) red[j >> 5] = c;
    __syncthreads();
    if (j == 0) {
        float s = 0.0f;
#pragma unroll
        for (int w = 0; w < 32; w++) s += red[w];
        g_slen[b] = s;
        g_lang[b] = (float)SS - s;
    }
}

// ---------------------------------------------------------------------------
// K1: pred[i,b] = sigmoid(x[i,b,:]·W + bias) * slen[b].  One warp per (i,b).
// ---------------------------------------------------------------------------
__global__ __launch_bounds__(256) void pred_kernel(
    const float* __restrict__ x, const float* __restrict__ W,
    const float* __restrict__ bias)
{
    int warp = (blockIdx.x * blockDim.x + threadIdx.x) >> 5;  // 0..S*B-1
    int lane = threadIdx.x & 31;
    int i = warp >> 5;   // B == 32
    int b = warp & 31;

    const float4* xv = (const float4*)(x + ((size_t)i * BB + b) * DD);
    const float4* wv = (const float4*)W;
    float sum = 0.0f;
#pragma unroll
    for (int t = 0; t < 8; t++) {
        float4 a = xv[t * 32 + lane];
        float4 w = wv[t * 32 + lane];
        sum += a.x * w.x + a.y * w.y + a.z * w.z + a.w * w.w;
    }
#pragma unroll
    for (int o = 16; o; o >>= 1) sum += __shfl_xor_sync(0xFFFFFFFFu, sum, o);
    if (lane == 0) {
        float t = sum + bias[0];
        float p = 1.0f / (1.0f + expf(-t));
        g_pred[i * BB + b] = p * g_slen[b];
    }
}

// ---------------------------------------------------------------------------
// K2: prob row for one (i,b): v_j = valid[b,j] / (d^2 + 1e-3), d = pred - (j - lang).
// Normalize over j; fold in the output row gate valid[b,i].
// Grid (S, B), 256 threads; each thread covers 4 j's. Stored (B, S, S).
// ---------------------------------------------------------------------------
__global__ __launch_bounds__(256) void prob_kernel() {
    int i = blockIdx.x;
    int b = blockIdx.y;
    int tid = threadIdx.x;

    float pr   = g_pred[i * BB + b];
    float lang = g_lang[b];
    const float* vrow = g_valid + b * SS;

    float v[4];
    float lsum = 0.0f;
#pragma unroll
    for (int t = 0; t < 4; t++) {
        int j = tid + t * 256;
        float d   = pr - ((float)j - lang);
        float val = vrow[j] / (d * d + 0.001f);
        v[t] = val;
        lsum += val;
    }

    __shared__ float red[8];
#pragma unroll
    for (int o = 16; o; o >>= 1) lsum += __shfl_xor_sync(0xFFFFFFFFu, lsum, o);
    if ((tid & 31) == 0) red[tid >> 5] = lsum;
    __syncthreads();
    if (tid == 0) {
        float s = 0.0f;
#pragma unroll
        for (int w = 0; w < 8; w++) s += red[w];
        float rowvalid = vrow[i];
        red[0] = (s > 0.0f) ? (rowvalid / s) : 0.0f;
    }
    __syncthreads();
    float scale = red[0];

    float* prow = g_prob + ((size_t)b * SS + i) * SS;
#pragma unroll
    for (int t = 0; t < 4; t++) {
        prow[tid + t * 256] = v[t] * scale;
    }
}

// ---------------------------------------------------------------------------
// K3: batched SGEMM.  Per batch b:  OUT_b[i,d] = sum_j P_b[i,j] * PE[j,b,d]
// Tile 64x64, BK=16, 256 threads, 4x4 micro-tile per thread.
// ---------------------------------------------------------------------------
__global__ __launch_bounds__(256) void gemm_kernel(
    const float* __restrict__ pe, float* __restrict__ out)
{
    const int b  = blockIdx.z;
    const int ti = blockIdx.y * 64;   // output row tile (i)
    const int td = blockIdx.x * 64;   // output col tile (d)

    __shared__ float As[16][64];
    __shared__ float Bs[16][64];

    const int tid = threadIdx.x;
    const int tx  = tid & 15;         // 0..15 -> 4 cols each
    const int ty  = tid >> 4;         // 0..15 -> 4 rows each

    const int arow = tid >> 2;        // 0..63
    const int acol = (tid & 3) << 2;  // 0,4,8,12
    const int brow = tid >> 4;        // 0..15
    const int bcol = (tid & 15) << 2; // 0..60

    const float* Ab = g_prob + (size_t)b * SS * SS + (size_t)(ti + arow) * SS + acol;
    const float* Bb = pe + (size_t)brow * (BB * DD) + (size_t)b * DD + td + bcol;

    float acc[4][4] = {};

    for (int k0 = 0; k0 < SS; k0 += 16) {
        float4 av = *(const float4*)(Ab + k0);
        float4 bv = *(const float4*)(Bb + (size_t)k0 * (BB * DD));

        As[acol + 0][arow] = av.x;
        As[acol + 1][arow] = av.y;
        As[acol + 2][arow] = av.z;
        As[acol + 3][arow] = av.w;
        *(float4*)&Bs[brow][bcol] = bv;
        __syncthreads();

#pragma unroll
        for (int k = 0; k < 16; k++) {
            float4 a  = *(const float4*)&As[k][ty << 2];
            float4 bb = *(const float4*)&Bs[k][tx << 2];
            acc[0][0] += a.x * bb.x; acc[0][1] += a.x * bb.y; acc[0][2] += a.x * bb.z; acc[0][3] += a.x * bb.w;
            acc[1][0] += a.y * bb.x; acc[1][1] += a.y * bb.y; acc[1][2] += a.y * bb.z; acc[1][3] += a.y * bb.w;
            acc[2][0] += a.z * bb.x; acc[2][1] += a.z * bb.y; acc[2][2] += a.z * bb.z; acc[2][3] += a.z * bb.w;
            acc[3][0] += a.w * bb.x; acc[3][1] += a.w * bb.y; acc[3][2] += a.w * bb.z; acc[3][3] += a.w * bb.w;
        }
        __syncthreads();
    }

#pragma unroll
    for (int m = 0; m < 4; m++) {
        int i = ti + (ty << 2) + m;
        float* op = out + (size_t)i * (BB * DD) + (size_t)b * DD + td + (tx << 2);
        *(float4*)op = make_float4(acc[m][0], acc[m][1], acc[m][2], acc[m][3]);
    }
}

// ---------------------------------------------------------------------------
// Launch. Inputs (metadata order):
//   0: x (S*B*D) f32, 1: layer_input (unused), 2: position_embedding (S*B*D) f32,
//   3: encoder_mask (B*S) bool (dtype sniffed), 4: W (D) f32, 5: b (1) f32
// Output: (S,B,D) f32
// ---------------------------------------------------------------------------
extern "C" void kernel_launch(void* const* d_in, const int* in_sizes, int n_in,
                              void* d_out, int out_size) {
    const float* x    = (const float*)d_in[0];
    const float* pe   = (const float*)d_in[2];
    const void*  mask = d_in[3];
    const float* W    = (const float*)d_in[4];
    const float* bias = (const float*)d_in[5];
    float*       out  = (float*)d_out;

    sniff_kernel<<<1, 256>>>((const int*)mask);
    mask_kernel<<<BB, 1024>>>(mask);
    pred_kernel<<<(SS * BB) / 8, 256>>>(x, W, bias);

    dim3 pgrid(SS, BB);
    prob_kernel<<<pgrid, 256>>>();

    dim3 ggrid(DD / 64, SS / 64, BB);
    gemm_kernel<<<ggrid, 256>>>(pe, out);
}

// round 3
// speedup vs baseline: 2.2130x; 2.2130x over previous
#include <cuda_runtime.h>
#include <cuda_bf16.h>
#include <math.h>
#include <stdint.h>

// Problem constants
#define SS 1024   // sequence length S
#define BB 32     // batch B
#define DD 1024   // model dim D

// Scratch (device globals — allocation-guard-safe)
__device__ float g_prob[(size_t)BB * SS * SS];   // (B, S, S) row-normalized, row-gated
__device__ float g_pred[SS * BB];                // (S, B)
__device__ float g_valid[BB * SS];               // (B, S) 1.0 = valid (not pad)
__device__ float g_slen[BB];
__device__ float g_lang[BB];
__device__ int   g_mask_is_i32;                  // 1 if mask delivered as int32

// ---------------------------------------------------------------------------
// K-1: sniff the mask dtype (bool delivered as uint8 or int32).
// ---------------------------------------------------------------------------
__global__ void sniff_kernel(const int* __restrict__ m) {
    __shared__ int bad[256];
    int tid = threadIdx.x;
    int any = 0;
#pragma unroll
    for (int t = 0; t < 32; t++) {
        int v = m[t * 256 + tid];
        any |= ((unsigned)v > 1u) ? 1 : 0;
    }
    bad[tid] = any;
    __syncthreads();
    if (tid == 0) {
        int a = 0;
        for (int k = 0; k < 256; k++) a |= bad[k];
        g_mask_is_i32 = a ? 0 : 1;
    }
}

// ---------------------------------------------------------------------------
// K0: expand mask to float valid array + per-batch reduction.
// ---------------------------------------------------------------------------
__global__ __launch_bounds__(1024) void mask_kernel(const void* __restrict__ maskp) {
    int b = blockIdx.x;
    int j = threadIdx.x;

    int mv;
    if (g_mask_is_i32) mv = ((const int*)maskp)[b * SS + j];
    else               mv = ((const unsigned char*)maskp)[b * SS + j];

    float valid = (mv == 0) ? 1.0f : 0.0f;
    g_valid[b * SS + j] = valid;

    __shared__ float red[32];
    float c = valid;
#pragma unroll
    for (int o = 16; o; o >>= 1) c += __shfl_xor_sync(0xFFFFFFFFu, c, o);
    if ((j & 31) == 0) red[j >> 5] = c;
    __syncthreads();
    if (j == 0) {
        float s = 0.0f;
#pragma unroll
        for (int w = 0; w < 32; w++) s += red[w];
        g_slen[b] = s;
        g_lang[b] = (float)SS - s;
    }
}

// ---------------------------------------------------------------------------
// K1: pred[i,b] = sigmoid(x[i,b,:]·W + bias) * slen[b].  One warp per (i,b).
// ---------------------------------------------------------------------------
__global__ __launch_bounds__(256) void pred_kernel(
    const float* __restrict__ x, const float* __restrict__ W,
    const float* __restrict__ bias)
{
    int warp = (blockIdx.x * blockDim.x + threadIdx.x) >> 5;
    int lane = threadIdx.x & 31;
    int i = warp >> 5;
    int b = warp & 31;

    const float4* xv = (const float4*)(x + ((size_t)i * BB + b) * DD);
    const float4* wv = (const float4*)W;
    float sum = 0.0f;
#pragma unroll
    for (int t = 0; t < 8; t++) {
        float4 a = xv[t * 32 + lane];
        float4 w = wv[t * 32 + lane];
        sum += a.x * w.x + a.y * w.y + a.z * w.z + a.w * w.w;
    }
#pragma unroll
    for (int o = 16; o; o >>= 1) sum += __shfl_xor_sync(0xFFFFFFFFu, sum, o);
    if (lane == 0) {
        float t = sum + bias[0];
        float p = 1.0f / (1.0f + expf(-t));
        g_pred[i * BB + b] = p * g_slen[b];
    }
}

// ---------------------------------------------------------------------------
// K2: normalized, gated prob row for one (i,b). Stored (B, S, S).
// ---------------------------------------------------------------------------
__global__ __launch_bounds__(256) void prob_kernel() {
    int i = blockIdx.x;
    int b = blockIdx.y;
    int tid = threadIdx.x;

    float pr   = g_pred[i * BB + b];
    float lang = g_lang[b];
    const float* vrow = g_valid + b * SS;

    float v[4];
    float lsum = 0.0f;
#pragma unroll
    for (int t = 0; t < 4; t++) {
        int j = tid + t * 256;
        float d   = pr - ((float)j - lang);
        float val = vrow[j] / (d * d + 0.001f);
        v[t] = val;
        lsum += val;
    }

    __shared__ float red[8];
#pragma unroll
    for (int o = 16; o; o >>= 1) lsum += __shfl_xor_sync(0xFFFFFFFFu, lsum, o);
    if ((tid & 31) == 0) red[tid >> 5] = lsum;
    __syncthreads();
    if (tid == 0) {
        float s = 0.0f;
#pragma unroll
        for (int w = 0; w < 8; w++) s += red[w];
        red[0] = (s > 0.0f) ? (vrow[i] / s) : 0.0f;
    }
    __syncthreads();
    float scale = red[0];

    float* prow = g_prob + ((size_t)b * SS + i) * SS;
#pragma unroll
    for (int t = 0; t < 4; t++) {
        prow[tid + t * 256] = v[t] * scale;
    }
}

// ---------------------------------------------------------------------------
// K3: batched GEMM via tf32 mma.sync (tensor cores).
// Per batch b: OUT[i,d] = sum_j P[b,i,j] * PE[j,b,d]
// Block tile 128x128, BK=32. 256 threads = 8 warps (2 m x 4 n), warp tile 64x32.
// mma.m16n8k8: 4 m-frags x 4 n-frags per warp, 4 k-steps per BK tile.
// Single-buffer smem + register prefetch of next K tile.
// ---------------------------------------------------------------------------
#define ASTRIDE 33    // padded smem row stride for A (128 x 32)
#define BSTRIDE 132   // padded smem row stride for B (32 x 128)

__device__ __forceinline__ uint32_t f2tf32(float x) {
    uint32_t u;
    asm("cvt.rna.tf32.f32 %0, %1;" : "=r"(u) : "f"(x));
    return u;
}

__global__ __launch_bounds__(256) void gemm_tf32_kernel(
    const float* __restrict__ pe, float* __restrict__ out)
{
    const int b  = blockIdx.z;
    const int ti = blockIdx.y * 128;  // output row tile (i)
    const int td = blockIdx.x * 128;  // output col tile (d)

    __shared__ float As[128 * ASTRIDE];
    __shared__ float Bs[32 * BSTRIDE];

    const int tid  = threadIdx.x;
    const int lane = tid & 31;
    const int warp = tid >> 5;
    const int wm   = warp & 1;        // 0..1  (m)
    const int wn   = warp >> 1;       // 0..3  (n)
    const int gid  = lane >> 2;       // group id 0..7
    const int tig  = lane & 3;        // thread in group 0..3

    // Global load mappings (fully coalesced, 128B per 8-thread group)
    const int arow = tid >> 3;        // 0..31 (+32*t)
    const int acol = (tid & 7) * 4;   // float4 col in 32-float row? -> floats
    const int bk   = tid >> 3;        // 0..31
    // B float4 col index: (tid&7) + 8*t  (covers 32 float4 = 128 floats)

    const float* Abase = g_prob + (size_t)b * SS * SS + (size_t)ti * SS;
    const float* Bbase = pe + (size_t)b * DD + td;

    float acc[4][4][4];
#pragma unroll
    for (int mf = 0; mf < 4; mf++)
#pragma unroll
        for (int nf = 0; nf < 4; nf++)
#pragma unroll
            for (int r = 0; r < 4; r++) acc[mf][nf][r] = 0.0f;

    float4 pa[4], pb[4];

    // Prefetch first K tile (k0 = 0)
#pragma unroll
    for (int t = 0; t < 4; t++) {
        pa[t] = *(const float4*)(Abase + (size_t)(arow + 32 * t) * SS + acol);
        pb[t] = *(const float4*)(Bbase + (size_t)bk * (BB * DD) + ((tid & 7) + 8 * t) * 4);
    }

    const int NK = SS / 32;
    for (int kt = 0; kt < NK; kt++) {
        __syncthreads();  // previous compute done before overwriting smem

        // Store prefetched tile to smem with tf32 conversion
#pragma unroll
        for (int t = 0; t < 4; t++) {
            float* ap = As + (arow + 32 * t) * ASTRIDE + acol;
            ap[0] = __uint_as_float(f2tf32(pa[t].x));
            ap[1] = __uint_as_float(f2tf32(pa[t].y));
            ap[2] = __uint_as_float(f2tf32(pa[t].z));
            ap[3] = __uint_as_float(f2tf32(pa[t].w));
            float* bp = Bs + bk * BSTRIDE + ((tid & 7) + 8 * t) * 4;
            bp[0] = __uint_as_float(f2tf32(pb[t].x));
            bp[1] = __uint_as_float(f2tf32(pb[t].y));
            bp[2] = __uint_as_float(f2tf32(pb[t].z));
            bp[3] = __uint_as_float(f2tf32(pb[t].w));
        }
        __syncthreads();

        // Prefetch next tile
        if (kt + 1 < NK) {
            int k0 = (kt + 1) * 32;
#pragma unroll
            for (int t = 0; t < 4; t++) {
                pa[t] = *(const float4*)(Abase + (size_t)(arow + 32 * t) * SS + k0 + acol);
                pb[t] = *(const float4*)(Bbase + (size_t)(k0 + bk) * (BB * DD) + ((tid & 7) + 8 * t) * 4);
            }
        }

        // Compute: 4 k-steps of m16n8k8
#pragma unroll
        for (int ks = 0; ks < 32; ks += 8) {
            uint32_t afr[4][4];
#pragma unroll
            for (int mf = 0; mf < 4; mf++) {
                int r0 = wm * 64 + mf * 16 + gid;
                afr[mf][0] = __float_as_uint(As[(r0    ) * ASTRIDE + ks + tig    ]);
                afr[mf][1] = __float_as_uint(As[(r0 + 8) * ASTRIDE + ks + tig    ]);
                afr[mf][2] = __float_as_uint(As[(r0    ) * ASTRIDE + ks + tig + 4]);
                afr[mf][3] = __float_as_uint(As[(r0 + 8) * ASTRIDE + ks + tig + 4]);
            }
            uint32_t bfr[4][2];
#pragma unroll
            for (int nf = 0; nf < 4; nf++) {
                int c0 = wn * 32 + nf * 8 + gid;
                bfr[nf][0] = __float_as_uint(Bs[(ks + tig    ) * BSTRIDE + c0]);
                bfr[nf][1] = __float_as_uint(Bs[(ks + tig + 4) * BSTRIDE + c0]);
            }
#pragma unroll
            for (int mf = 0; mf < 4; mf++) {
#pragma unroll
                for (int nf = 0; nf < 4; nf++) {
                    asm volatile(
                        "mma.sync.aligned.m16n8k8.row.col.f32.tf32.tf32.f32 "
                        "{%0,%1,%2,%3}, {%4,%5,%6,%7}, {%8,%9}, {%0,%1,%2,%3};"
                        : "+f"(acc[mf][nf][0]), "+f"(acc[mf][nf][1]),
                          "+f"(acc[mf][nf][2]), "+f"(acc[mf][nf][3])
                        : "r"(afr[mf][0]), "r"(afr[mf][1]),
                          "r"(afr[mf][2]), "r"(afr[mf][3]),
                          "r"(bfr[nf][0]), "r"(bfr[nf][1]));
                }
            }
        }
    }

    // Store C. c0: (gid, tig*2) c1: (gid, tig*2+1) c2: (gid+8, tig*2) c3: (+8,+1)
#pragma unroll
    for (int mf = 0; mf < 4; mf++) {
#pragma unroll
        for (int nf = 0; nf < 4; nf++) {
            int row0 = ti + wm * 64 + mf * 16 + gid;
            int col  = td + wn * 32 + nf * 8 + tig * 2;
            float* o0 = out + (size_t)row0 * (BB * DD) + (size_t)b * DD + col;
            float* o1 = out + (size_t)(row0 + 8) * (BB * DD) + (size_t)b * DD + col;
            o0[0] = acc[mf][nf][0];
            o0[1] = acc[mf][nf][1];
            o1[0] = acc[mf][nf][2];
            o1[1] = acc[mf][nf][3];
        }
    }
}

// ---------------------------------------------------------------------------
// Launch. Inputs: 0:x 1:layer_input(unused) 2:pe 3:encoder_mask 4:W 5:b
// ---------------------------------------------------------------------------
extern "C" void kernel_launch(void* const* d_in, const int* in_sizes, int n_in,
                              void* d_out, int out_size) {
    const float* x    = (const float*)d_in[0];
    const float* pe   = (const float*)d_in[2];
    const void*  mask = d_in[3];
    const float* W    = (const float*)d_in[4];
    const float* bias = (const float*)d_in[5];
    float*       out  = (float*)d_out;

    sniff_kernel<<<1, 256>>>((const int*)mask);
    mask_kernel<<<BB, 1024>>>(mask);
    pred_kernel<<<(SS * BB) / 8, 256>>>(x, W, bias);

    dim3 pgrid(SS, BB);
    prob_kernel<<<pgrid, 256>>>();

    dim3 ggrid(DD / 128, SS / 128, BB);
    gemm_tf32_kernel<<<ggrid, 256>>>(pe, out);
}

// round 5
// speedup vs baseline: 4.4261x; 2.0001x over previous
#include <cuda_runtime.h>
#include <cuda_bf16.h>
#include <cuda_fp16.h>
#include <math.h>
#include <stdint.h>

// Problem constants
#define SS 1024   // sequence length S
#define BB 32     // batch B
#define DD 1024   // model dim D

// Scratch (device globals — allocation-guard-safe)
__device__ __half g_probH[(size_t)BB * SS * SS];   // (B, S, S) fp16
__device__ __half g_peT[(size_t)BB * DD * SS];     // (B, D, S) fp16
__device__ float g_pred[SS * BB];
__device__ float g_valid[BB * SS];
__device__ float g_slen[BB];
__device__ float g_lang[BB];
__device__ int   g_mask_is_i32;

// ---------------------------------------------------------------------------
// K-1: sniff the mask dtype (bool delivered as uint8 or int32).
// ---------------------------------------------------------------------------
__global__ void sniff_kernel(const int* __restrict__ m) {
    __shared__ int bad[256];
    int tid = threadIdx.x;
    int any = 0;
#pragma unroll
    for (int t = 0; t < 32; t++) {
        int v = m[t * 256 + tid];
        any |= ((unsigned)v > 1u) ? 1 : 0;
    }
    bad[tid] = any;
    __syncthreads();
    if (tid == 0) {
        int a = 0;
        for (int k = 0; k < 256; k++) a |= bad[k];
        g_mask_is_i32 = a ? 0 : 1;
    }
}

// ---------------------------------------------------------------------------
// K0: expand mask + per-batch reduction.
// ---------------------------------------------------------------------------
__global__ __launch_bounds__(1024) void mask_kernel(const void* __restrict__ maskp) {
    int b = blockIdx.x;
    int j = threadIdx.x;

    int mv;
    if (g_mask_is_i32) mv = ((const int*)maskp)[b * SS + j];
    else               mv = ((const unsigned char*)maskp)[b * SS + j];

    float valid = (mv == 0) ? 1.0f : 0.0f;
    g_valid[b * SS + j] = valid;

    __shared__ float red[32];
    float c = valid;
#pragma unroll
    for (int o = 16; o; o >>= 1) c += __shfl_xor_sync(0xFFFFFFFFu, c, o);
    if ((j & 31) == 0) red[j >> 5] = c;
    __syncthreads();
    if (j == 0) {
        float s = 0.0f;
#pragma unroll
        for (int w = 0; w < 32; w++) s += red[w];
        g_slen[b] = s;
        g_lang[b] = (float)SS - s;
    }
}

// ---------------------------------------------------------------------------
// K1: pred[i,b] = sigmoid(x[i,b,:]·W + bias) * slen[b].  One warp per (i,b).
// ---------------------------------------------------------------------------
__global__ __launch_bounds__(256) void pred_kernel(
    const float* __restrict__ x, const float* __restrict__ W,
    const float* __restrict__ bias)
{
    int warp = (blockIdx.x * blockDim.x + threadIdx.x) >> 5;
    int lane = threadIdx.x & 31;
    int i = warp >> 5;
    int b = warp & 31;

    const float4* xv = (const float4*)(x + ((size_t)i * BB + b) * DD);
    const float4* wv = (const float4*)W;
    float sum = 0.0f;
#pragma unroll
    for (int t = 0; t < 8; t++) {
        float4 a = xv[t * 32 + lane];
        float4 w = wv[t * 32 + lane];
        sum += a.x * w.x + a.y * w.y + a.z * w.z + a.w * w.w;
    }
#pragma unroll
    for (int o = 16; o; o >>= 1) sum += __shfl_xor_sync(0xFFFFFFFFu, sum, o);
    if (lane == 0) {
        float t = sum + bias[0];
        float p = 1.0f / (1.0f + expf(-t));
        g_pred[i * BB + b] = p * g_slen[b];
    }
}

// ---------------------------------------------------------------------------
// K2: normalized, gated prob row -> fp16, stored (B, S, S).
// ---------------------------------------------------------------------------
__global__ __launch_bounds__(256) void prob_kernel() {
    int i = blockIdx.x;
    int b = blockIdx.y;
    int tid = threadIdx.x;

    float pr   = g_pred[i * BB + b];
    float lang = g_lang[b];
    const float* vrow = g_valid + b * SS;

    float v[4];
    float lsum = 0.0f;
#pragma unroll
    for (int t = 0; t < 4; t++) {
        int j = tid + t * 256;
        float d   = pr - ((float)j - lang);
        float val = vrow[j] / (d * d + 0.001f);
        v[t] = val;
        lsum += val;
    }

    __shared__ float red[8];
#pragma unroll
    for (int o = 16; o; o >>= 1) lsum += __shfl_xor_sync(0xFFFFFFFFu, lsum, o);
    if ((tid & 31) == 0) red[tid >> 5] = lsum;
    __syncthreads();
    if (tid == 0) {
        float s = 0.0f;
#pragma unroll
        for (int w = 0; w < 8; w++) s += red[w];
        red[0] = (s > 0.0f) ? (vrow[i] / s) : 0.0f;
    }
    __syncthreads();
    float scale = red[0];

    size_t base = ((size_t)b * SS + i) * SS;
#pragma unroll
    for (int t = 0; t < 4; t++) {
        int j = tid + t * 256;
        g_probH[base + j] = __float2half_rn(v[t] * scale);
    }
}

// ---------------------------------------------------------------------------
// K2b: transpose pe (S,B,D) -> peT (B,D,S) fp16. 64x64 tile per block.
// ---------------------------------------------------------------------------
__global__ __launch_bounds__(256) void transpose_kernel(const float* __restrict__ pe) {
    __shared__ float t[64][65];
    int j0 = blockIdx.x * 64;
    int d0 = blockIdx.y * 64;
    int b  = blockIdx.z;
    int tid = threadIdx.x;

#pragma unroll
    for (int q = 0; q < 4; q++) {
        int idx = tid + 256 * q;          // 0..1023
        int jr  = idx >> 4;               // 0..63
        int c4  = idx & 15;
        float4 v = *(const float4*)(pe + ((size_t)(j0 + jr) * BB + b) * DD + d0 + c4 * 4);
        t[jr][c4 * 4 + 0] = v.x;
        t[jr][c4 * 4 + 1] = v.y;
        t[jr][c4 * 4 + 2] = v.z;
        t[jr][c4 * 4 + 3] = v.w;
    }
    __syncthreads();

#pragma unroll
    for (int q = 0; q < 4; q++) {
        int idx = tid + 256 * q;
        int dr  = idx >> 4;               // 0..63
        int c4  = idx & 15;               // 4 j's
        __half h[4];
#pragma unroll
        for (int k = 0; k < 4; k++) h[k] = __float2half_rn(t[c4 * 4 + k][dr]);
        size_t dst = ((size_t)b * DD + d0 + dr) * SS + j0 + c4 * 4;
        *(uint2*)&g_peT[dst] = *(uint2*)h;
    }
}

// ---------------------------------------------------------------------------
// K3: batched GEMM via fp16 mma.sync m16n8k16 (fp32 accumulate).
// Per batch b: OUT[i,d] = sum_j probH[b,i,j] * peT[b,d,j]
// Block tile 128x128, BK=32. 256 threads = 8 warps (2 m x 4 n), warp tile 64x32.
// Both operands K-major in smem; fragment reg pairs are contiguous 4B LDS.
// Single-buffer smem + register prefetch of next K tile.
// ---------------------------------------------------------------------------
#define AST 40   // padded smem row stride in halves (80B, 16B-aligned, bank-clean)

__global__ __launch_bounds__(256) void gemm_fp16_kernel(float* __restrict__ out) {
    const int b  = blockIdx.z;
    const int ti = blockIdx.y * 128;  // output row tile (i)
    const int td = blockIdx.x * 128;  // output col tile (d)

    __shared__ __half As[128 * AST];  // (m, k)
    __shared__ __half Bs[128 * AST];  // (n, k)

    const int tid  = threadIdx.x;
    const int lane = tid & 31;
    const int warp = tid >> 5;
    const int wm   = warp & 1;        // 0..1  (m)
    const int wn   = warp >> 1;       // 0..3  (n)
    const int gid  = lane >> 2;       // 0..7
    const int tig  = lane & 3;        // 0..3

    // Global->smem mapping: idx = tid + 256*t (t=0..1); row = idx>>2 (0..127),
    // q = idx&3 -> 8-half (16B) chunk within the 32-half row.
    const int grow = tid >> 2;
    const int gq   = (tid & 3) * 8;

    const __half* Ab = g_probH + ((size_t)b * SS + ti) * SS;
    const __half* Bb = g_peT   + ((size_t)b * DD + td) * SS;

    float acc[4][4][4];
#pragma unroll
    for (int mf = 0; mf < 4; mf++)
#pragma unroll
        for (int nf = 0; nf < 4; nf++)
#pragma unroll
            for (int r = 0; r < 4; r++) acc[mf][nf][r] = 0.0f;

    uint4 pa[2], pb[2];

    // Prefetch first K tile (k0 = 0)
#pragma unroll
    for (int t = 0; t < 2; t++) {
        pa[t] = *(const uint4*)(Ab + (size_t)(grow + 64 * t) * SS + gq);
        pb[t] = *(const uint4*)(Bb + (size_t)(grow + 64 * t) * SS + gq);
    }

    const int NK = SS / 32;
    for (int kt = 0; kt < NK; kt++) {
        __syncthreads();

#pragma unroll
        for (int t = 0; t < 2; t++) {
            *(uint4*)&As[(grow + 64 * t) * AST + gq] = pa[t];
            *(uint4*)&Bs[(grow + 64 * t) * AST + gq] = pb[t];
        }
        __syncthreads();

        if (kt + 1 < NK) {
            int k0 = (kt + 1) * 32;
#pragma unroll
            for (int t = 0; t < 2; t++) {
                pa[t] = *(const uint4*)(Ab + (size_t)(grow + 64 * t) * SS + k0 + gq);
                pb[t] = *(const uint4*)(Bb + (size_t)(grow + 64 * t) * SS + k0 + gq);
            }
        }

        // Compute: 2 k-steps of m16n8k16
#pragma unroll
        for (int ks = 0; ks < 32; ks += 16) {
            uint32_t afr[4][4];
#pragma unroll
            for (int mf = 0; mf < 4; mf++) {
                int r0 = wm * 64 + mf * 16 + gid;
                afr[mf][0] = *(const uint32_t*)&As[(r0    ) * AST + ks + tig * 2    ];
                afr[mf][1] = *(const uint32_t*)&As[(r0 + 8) * AST + ks + tig * 2    ];
                afr[mf][2] = *(const uint32_t*)&As[(r0    ) * AST + ks + tig * 2 + 8];
                afr[mf][3] = *(const uint32_t*)&As[(r0 + 8) * AST + ks + tig * 2 + 8];
            }
            uint32_t bfr[4][2];
#pragma unroll
            for (int nf = 0; nf < 4; nf++) {
                int c0 = wn * 32 + nf * 8 + gid;
                bfr[nf][0] = *(const uint32_t*)&Bs[c0 * AST + ks + tig * 2    ];
                bfr[nf][1] = *(const uint32_t*)&Bs[c0 * AST + ks + tig * 2 + 8];
            }
#pragma unroll
            for (int mf = 0; mf < 4; mf++) {
#pragma unroll
                for (int nf = 0; nf < 4; nf++) {
                    asm volatile(
                        "mma.sync.aligned.m16n8k16.row.col.f32.f16.f16.f32 "
                        "{%0,%1,%2,%3}, {%4,%5,%6,%7}, {%8,%9}, {%0,%1,%2,%3};"
                        : "+f"(acc[mf][nf][0]), "+f"(acc[mf][nf][1]),
                          "+f"(acc[mf][nf][2]), "+f"(acc[mf][nf][3])
                        : "r"(afr[mf][0]), "r"(afr[mf][1]),
                          "r"(afr[mf][2]), "r"(afr[mf][3]),
                          "r"(bfr[nf][0]), "r"(bfr[nf][1]));
                }
            }
        }
    }

    // Store C. c0/c1 at (gid, tig*2/+1); c2/c3 at (gid+8, same cols).
#pragma unroll
    for (int mf = 0; mf < 4; mf++) {
#pragma unroll
        for (int nf = 0; nf < 4; nf++) {
            int row0 = ti + wm * 64 + mf * 16 + gid;
            int col  = td + wn * 32 + nf * 8 + tig * 2;
            float* o0 = out + (size_t)row0 * (BB * DD) + (size_t)b * DD + col;
            float* o1 = out + (size_t)(row0 + 8) * (BB * DD) + (size_t)b * DD + col;
            o0[0] = acc[mf][nf][0];
            o0[1] = acc[mf][nf][1];
            o1[0] = acc[mf][nf][2];
            o1[1] = acc[mf][nf][3];
        }
    }
}

// ---------------------------------------------------------------------------
// Launch. Inputs: 0:x 1:layer_input(unused) 2:pe 3:encoder_mask 4:W 5:b
// ---------------------------------------------------------------------------
extern "C" void kernel_launch(void* const* d_in, const int* in_sizes, int n_in,
                              void* d_out, int out_size) {
    const float* x    = (const float*)d_in[0];
    const float* pe   = (const float*)d_in[2];
    const void*  mask = d_in[3];
    const float* W    = (const float*)d_in[4];
    const float* bias = (const float*)d_in[5];
    float*       out  = (float*)d_out;

    sniff_kernel<<<1, 256>>>((const int*)mask);
    mask_kernel<<<BB, 1024>>>(mask);
    pred_kernel<<<(SS * BB) / 8, 256>>>(x, W, bias);

    dim3 pgrid(SS, BB);
    prob_kernel<<<pgrid, 256>>>();

    dim3 tgrid(SS / 64, DD / 64, BB);
    transpose_kernel<<<tgrid, 256>>>(pe);

    dim3 ggrid(DD / 128, SS / 128, BB);
    gemm_fp16_kernel<<<ggrid, 256>>>(out);
}